// round 5
// baseline (speedup 1.0000x reference)
#include <cuda_runtime.h>
#include <cuda_bf16.h>
#include <stdint.h>
#include <math.h>

#define BATCH 2
#define SEQ   2048
#define DM    1024
#define NH    16
#define DH    64

// Scratch (allocation-free rule: __device__ globals)
__device__ float g_q[BATCH*SEQ*DM];
__device__ float g_k[BATCH*SEQ*DM];
__device__ float g_v[BATCH*SEQ*DM];
__device__ float g_attn[BATCH*SEQ*DM];

// ============================================================================
// Helpers
// ============================================================================
__device__ __forceinline__ uint32_t smem_u32(const void* p) {
    uint32_t a;
    asm("{ .reg .u64 t; cvta.to.shared.u64 t, %1; cvt.u32.u64 %0, t; }"
        : "=r"(a) : "l"(p));
    return a;
}

__device__ __forceinline__ void ldmatrix_x4(uint32_t* r, uint32_t addr) {
    asm volatile("ldmatrix.sync.aligned.m8n8.x4.shared.b16 {%0,%1,%2,%3}, [%4];"
                 : "=r"(r[0]), "=r"(r[1]), "=r"(r[2]), "=r"(r[3]) : "r"(addr));
}

__device__ __forceinline__ void ldmatrix_x4_trans(uint32_t* r, uint32_t addr) {
    asm volatile("ldmatrix.sync.aligned.m8n8.x4.trans.shared.b16 {%0,%1,%2,%3}, [%4];"
                 : "=r"(r[0]), "=r"(r[1]), "=r"(r[2]), "=r"(r[3]) : "r"(addr));
}

__device__ __forceinline__ void mma_bf16(float* d, const uint32_t* a, const uint32_t* b,
                                         const float* c) {
    asm volatile(
        "mma.sync.aligned.m16n8k16.row.col.f32.bf16.bf16.f32 "
        "{%0,%1,%2,%3}, {%4,%5,%6,%7}, {%8,%9}, {%10,%11,%12,%13};"
        : "=f"(d[0]), "=f"(d[1]), "=f"(d[2]), "=f"(d[3])
        : "r"(a[0]), "r"(a[1]), "r"(a[2]), "r"(a[3]),
          "r"(b[0]), "r"(b[1]),
          "f"(c[0]), "f"(c[1]), "f"(c[2]), "f"(c[3]));
}

__device__ __forceinline__ void pack_hilo(float x, float y, uint32_t& hi, uint32_t& lo) {
    __nv_bfloat16 hx = __float2bfloat16(x);
    __nv_bfloat16 hy = __float2bfloat16(y);
    __nv_bfloat16 lx = __float2bfloat16(x - __bfloat162float(hx));
    __nv_bfloat16 ly = __float2bfloat16(y - __bfloat162float(hy));
    hi = (uint32_t)__bfloat16_as_ushort(hx) | ((uint32_t)__bfloat16_as_ushort(hy) << 16);
    lo = (uint32_t)__bfloat16_as_ushort(lx) | ((uint32_t)__bfloat16_as_ushort(ly) << 16);
}

// ============================================================================
// Split-bf16 tensor-core GEMM (validated R3/R4):  C = A @ W^T + bias
// ============================================================================
#define GKC    64
#define TSTRB  144
#define TILE_B (128 * TSTRB)
#define OFF_AHI 0
#define OFF_ALO (TILE_B)
#define OFF_BHI (2 * TILE_B)
#define OFF_BLO (3 * TILE_B)
#define GEMM_SMEM (4 * TILE_B)

__device__ __forceinline__ void cvt_store_pair(char* hi_b, char* lo_b,
                                               int row, int c4, float4 v) {
    __nv_bfloat16 h0 = __float2bfloat16(v.x);
    __nv_bfloat16 h1 = __float2bfloat16(v.y);
    __nv_bfloat16 h2 = __float2bfloat16(v.z);
    __nv_bfloat16 h3 = __float2bfloat16(v.w);
    __nv_bfloat16 l0 = __float2bfloat16(v.x - __bfloat162float(h0));
    __nv_bfloat16 l1 = __float2bfloat16(v.y - __bfloat162float(h1));
    __nv_bfloat16 l2 = __float2bfloat16(v.z - __bfloat162float(h2));
    __nv_bfloat16 l3 = __float2bfloat16(v.w - __bfloat162float(h3));
    uint32_t off = (uint32_t)(row * TSTRB + c4 * 8);
    uint2 hp, lp;
    hp.x = (uint32_t)__bfloat16_as_ushort(h0) | ((uint32_t)__bfloat16_as_ushort(h1) << 16);
    hp.y = (uint32_t)__bfloat16_as_ushort(h2) | ((uint32_t)__bfloat16_as_ushort(h3) << 16);
    lp.x = (uint32_t)__bfloat16_as_ushort(l0) | ((uint32_t)__bfloat16_as_ushort(l1) << 16);
    lp.y = (uint32_t)__bfloat16_as_ushort(l2) | ((uint32_t)__bfloat16_as_ushort(l3) << 16);
    *(uint2*)(hi_b + off) = hp;
    *(uint2*)(lo_b + off) = lp;
}

__global__ void __launch_bounds__(256) gemm_tc_kernel(const float* __restrict__ A,
                                                      const float* __restrict__ W,
                                                      const float* __restrict__ bias,
                                                      float* __restrict__ C,
                                                      int M, int N, int K) {
    extern __shared__ char tile[];

    const int tid = threadIdx.x;
    const int wid = tid >> 5;
    const int lane = tid & 31;
    const int m0 = blockIdx.y * 128;
    const int n0 = blockIdx.x * 128;
    const int wm = wid >> 1;
    const int wn = wid & 1;

    const uint32_t tile_u = smem_u32(tile);

    float acc[2][8][4];
    #pragma unroll
    for (int i = 0; i < 2; i++)
        #pragma unroll
        for (int j = 0; j < 8; j++)
            #pragma unroll
            for (int t = 0; t < 4; t++) acc[i][j][t] = 0.f;

    const uint32_t a_row = (uint32_t)(wm * 32 + (lane & 15));
    const uint32_t a_kof = (uint32_t)((lane >> 4) * 8) * 2;
    const uint32_t b_row = (uint32_t)(wn * 64 + (lane & 7) + ((lane >> 4) & 1) * 8);
    const uint32_t b_kof = (uint32_t)(((lane >> 3) & 1) * 8) * 2;

    const int nchunk = K / GKC;
    for (int c = 0; c < nchunk; ++c) {
        const int k0 = c * GKC;
        float4 ra[8], rb[8];
        #pragma unroll
        for (int i = 0; i < 8; i++) {
            int f4 = tid + i * 256;
            int row = f4 >> 4, c4 = f4 & 15;
            ra[i] = *(const float4*)(A + (size_t)(m0 + row) * K + k0 + c4 * 4);
            rb[i] = *(const float4*)(W + (size_t)(n0 + row) * K + k0 + c4 * 4);
        }
        __syncthreads();
        #pragma unroll
        for (int i = 0; i < 8; i++) {
            int f4 = tid + i * 256;
            int row = f4 >> 4, c4 = f4 & 15;
            cvt_store_pair(tile + OFF_AHI, tile + OFF_ALO, row, c4, ra[i]);
            cvt_store_pair(tile + OFF_BHI, tile + OFF_BLO, row, c4, rb[i]);
        }
        __syncthreads();

        #pragma unroll
        for (int ks = 0; ks < 4; ks++) {
            const uint32_t kbyte = (uint32_t)(ks * 16) * 2;
            uint32_t aHi[2][4], aLo[2][4], bHi[4][4], bLo[4][4];
            #pragma unroll
            for (int mi = 0; mi < 2; mi++) {
                uint32_t ar = tile_u + (a_row + mi * 16) * TSTRB + kbyte + a_kof;
                ldmatrix_x4(aHi[mi], ar + OFF_AHI);
                ldmatrix_x4(aLo[mi], ar + OFF_ALO);
            }
            #pragma unroll
            for (int nt2 = 0; nt2 < 4; nt2++) {
                uint32_t br = tile_u + (b_row + nt2 * 16) * TSTRB + kbyte + b_kof;
                ldmatrix_x4(bHi[nt2], br + OFF_BHI);
                ldmatrix_x4(bLo[nt2], br + OFF_BLO);
            }
            #pragma unroll
            for (int mi = 0; mi < 2; mi++)
                #pragma unroll
                for (int nt = 0; nt < 8; nt++) {
                    const uint32_t* bh = &bHi[nt >> 1][(nt & 1) * 2];
                    const uint32_t* bl = &bLo[nt >> 1][(nt & 1) * 2];
                    mma_bf16(acc[mi][nt], aHi[mi], bh, acc[mi][nt]);
                    mma_bf16(acc[mi][nt], aHi[mi], bl, acc[mi][nt]);
                    mma_bf16(acc[mi][nt], aLo[mi], bh, acc[mi][nt]);
                }
        }
    }

    const int er = lane >> 2;
    const int ec = (lane & 3) * 2;
    #pragma unroll
    for (int mi = 0; mi < 2; mi++) {
        int row0 = m0 + wm * 32 + mi * 16 + er;
        #pragma unroll
        for (int nt = 0; nt < 8; nt++) {
            int col = n0 + wn * 64 + nt * 8 + ec;
            float b0 = __ldg(bias + col), b1 = __ldg(bias + col + 1);
            float2 o0 = make_float2(acc[mi][nt][0] + b0, acc[mi][nt][1] + b1);
            float2 o1 = make_float2(acc[mi][nt][2] + b0, acc[mi][nt][3] + b1);
            *(float2*)(C + (size_t)row0 * N + col) = o0;
            *(float2*)(C + (size_t)(row0 + 8) * N + col) = o1;
        }
    }
}

// ============================================================================
// Tensor-core flash attention. CTA = (b, h, 64 q-rows), 4 warps x 16 rows.
// KV tile 64. Split-bf16 3-pass QK^T and PV. KV register-prefetch before the
// barrier so LDG latency overlaps the previous tile's MMA work.
// ============================================================================
#define KV_T    64
#define KVT_B   (64 * TSTRB)               // 9216 per half-tile
#define ATT_SMEM (4 * KVT_B + 256)         // 37120

__global__ void __launch_bounds__(128) attn_tc_kernel(const float* __restrict__ q,
                                                      const float* __restrict__ k,
                                                      const float* __restrict__ v,
                                                      const int*   __restrict__ mask,
                                                      float* __restrict__ out) {
    extern __shared__ char sm[];
    float* msel = (float*)(sm + 4 * KVT_B);   // 64 mask flags

    const int b  = blockIdx.z;
    const int h  = blockIdx.y;
    const int q0 = blockIdx.x * 64;
    const int tid  = threadIdx.x;
    const int wid  = tid >> 5;    // 0..3
    const int lane = tid & 31;

    const uint32_t u_base = smem_u32(sm);
    const uint32_t u_khi = u_base;
    const uint32_t u_klo = u_base + KVT_B;
    const uint32_t u_vhi = u_base + 2 * KVT_B;
    const uint32_t u_vlo = u_base + 3 * KVT_B;

    // ---- Phase 1: load Q (scaled by 1/8), split to hi/lo smem, build frags ----
    #pragma unroll
    for (int i = 0; i < 8; i++) {
        int f4 = tid + i * 128;            // 64 rows x 16 float4
        int row = f4 >> 4, c4 = f4 & 15;
        float4 val = *(const float4*)(q + (size_t)(b * SEQ + q0 + row) * DM + h * DH + c4 * 4);
        val.x *= 0.125f; val.y *= 0.125f; val.z *= 0.125f; val.w *= 0.125f;
        cvt_store_pair(sm, sm + KVT_B, row, c4, val);
    }
    __syncthreads();

    uint32_t qHi[4][4], qLo[4][4];
    {
        const uint32_t qrow = (uint32_t)(wid * 16 + (lane & 15));
        const uint32_t qkof = (uint32_t)((lane >> 4) * 8) * 2;
        #pragma unroll
        for (int ks = 0; ks < 4; ks++) {
            uint32_t addr = u_base + qrow * TSTRB + (uint32_t)(ks * 32) + qkof;
            ldmatrix_x4(qHi[ks], addr);
            ldmatrix_x4(qLo[ks], addr + KVT_B);
        }
    }
    __syncthreads();   // Q smem now reusable for K/V

    // ---- main loop state ----
    float m0 = -1e30f, m1 = -1e30f, l0 = 0.f, l1 = 0.f;
    float oAcc[8][4];
    #pragma unroll
    for (int nt = 0; nt < 8; nt++)
        #pragma unroll
        for (int t = 0; t < 4; t++) oAcc[nt][t] = 0.f;

    const uint32_t krow_b = (uint32_t)((lane & 7) + ((lane >> 4) & 1) * 8);
    const uint32_t kk_b   = (uint32_t)(((lane >> 3) & 1) * 8) * 2;
    const uint32_t vrow_b = (uint32_t)(lane & 15);
    const uint32_t vcol_b = (uint32_t)(((lane >> 4) & 1) * 8) * 2;
    const int mcol = (lane & 3) * 2;

    for (int j0 = 0; j0 < SEQ; j0 += KV_T) {
        // ---- prefetch K/V + mask into registers BEFORE the barrier ----
        float4 rk[8], rv[8];
        #pragma unroll
        for (int i = 0; i < 8; i++) {
            int f4 = tid + i * 128;        // 64 rows x 16 float4
            int row = f4 >> 4, c4 = f4 & 15;
            size_t g = (size_t)(b * SEQ + j0 + row) * DM + h * DH + c4 * 4;
            rk[i] = *(const float4*)(k + g);
            rv[i] = *(const float4*)(v + g);
        }
        int mval = (tid < KV_T) ? mask[b * SEQ + j0 + tid] : 0;

        __syncthreads();   // previous tile fully consumed
        #pragma unroll
        for (int i = 0; i < 8; i++) {
            int f4 = tid + i * 128;
            int row = f4 >> 4, c4 = f4 & 15;
            cvt_store_pair((char*)sm,             (char*)sm + KVT_B,     row, c4, rk[i]);
            cvt_store_pair((char*)sm + 2 * KVT_B, (char*)sm + 3 * KVT_B, row, c4, rv[i]);
        }
        if (tid < KV_T) msel[tid] = (float)mval;
        __syncthreads();

        // ---- S = Q @ K^T (3 passes) ----
        float sAcc[8][4];
        #pragma unroll
        for (int nt = 0; nt < 8; nt++)
            #pragma unroll
            for (int t = 0; t < 4; t++) sAcc[nt][t] = 0.f;

        #pragma unroll
        for (int ks = 0; ks < 4; ks++) {
            const uint32_t kbyte = (uint32_t)(ks * 16) * 2;
            uint32_t kH[4][4], kL[4][4];
            #pragma unroll
            for (int nt2 = 0; nt2 < 4; nt2++) {
                uint32_t addr = u_khi + (uint32_t)(nt2 * 16 + krow_b) * TSTRB + kbyte + kk_b;
                ldmatrix_x4(kH[nt2], addr);
                ldmatrix_x4(kL[nt2], addr + KVT_B);
            }
            #pragma unroll
            for (int nt = 0; nt < 8; nt++) {
                const uint32_t* bh = &kH[nt >> 1][(nt & 1) * 2];
                const uint32_t* bl = &kL[nt >> 1][(nt & 1) * 2];
                mma_bf16(sAcc[nt], qHi[ks], bh, sAcc[nt]);
                mma_bf16(sAcc[nt], qHi[ks], bl, sAcc[nt]);
                mma_bf16(sAcc[nt], qLo[ks], bh, sAcc[nt]);
            }
        }

        // ---- mask + online softmax ----
        float rm0 = -1e30f, rm1 = -1e30f;
        #pragma unroll
        for (int nt = 0; nt < 8; nt++) {
            float2 mf = *(const float2*)(msel + nt * 8 + mcol);
            float s0 = (mf.x != 0.f) ? sAcc[nt][0] : -1e9f;
            float s1 = (mf.y != 0.f) ? sAcc[nt][1] : -1e9f;
            float s2 = (mf.x != 0.f) ? sAcc[nt][2] : -1e9f;
            float s3 = (mf.y != 0.f) ? sAcc[nt][3] : -1e9f;
            sAcc[nt][0] = s0; sAcc[nt][1] = s1; sAcc[nt][2] = s2; sAcc[nt][3] = s3;
            rm0 = fmaxf(rm0, fmaxf(s0, s1));
            rm1 = fmaxf(rm1, fmaxf(s2, s3));
        }
        rm0 = fmaxf(rm0, __shfl_xor_sync(0xffffffffu, rm0, 1));
        rm0 = fmaxf(rm0, __shfl_xor_sync(0xffffffffu, rm0, 2));
        rm1 = fmaxf(rm1, __shfl_xor_sync(0xffffffffu, rm1, 1));
        rm1 = fmaxf(rm1, __shfl_xor_sync(0xffffffffu, rm1, 2));

        float m0n = fmaxf(m0, rm0), m1n = fmaxf(m1, rm1);
        float a0 = __expf(m0 - m0n), a1 = __expf(m1 - m1n);
        float ps0 = 0.f, ps1 = 0.f;
        #pragma unroll
        for (int nt = 0; nt < 8; nt++) {
            float p0 = __expf(sAcc[nt][0] - m0n);
            float p1 = __expf(sAcc[nt][1] - m0n);
            float p2 = __expf(sAcc[nt][2] - m1n);
            float p3 = __expf(sAcc[nt][3] - m1n);
            sAcc[nt][0] = p0; sAcc[nt][1] = p1; sAcc[nt][2] = p2; sAcc[nt][3] = p3;
            ps0 += p0 + p1; ps1 += p2 + p3;
            oAcc[nt][0] *= a0; oAcc[nt][1] *= a0;
            oAcc[nt][2] *= a1; oAcc[nt][3] *= a1;
        }
        ps0 += __shfl_xor_sync(0xffffffffu, ps0, 1);
        ps0 += __shfl_xor_sync(0xffffffffu, ps0, 2);
        ps1 += __shfl_xor_sync(0xffffffffu, ps1, 1);
        ps1 += __shfl_xor_sync(0xffffffffu, ps1, 2);
        l0 = l0 * a0 + ps0;
        l1 = l1 * a1 + ps1;
        m0 = m0n; m1 = m1n;

        // ---- O += P @ V (3 passes) ----
        #pragma unroll
        for (int ks = 0; ks < 4; ks++) {
            uint32_t aH[4], aL[4];
            pack_hilo(sAcc[2 * ks][0],     sAcc[2 * ks][1],     aH[0], aL[0]);
            pack_hilo(sAcc[2 * ks][2],     sAcc[2 * ks][3],     aH[1], aL[1]);
            pack_hilo(sAcc[2 * ks + 1][0], sAcc[2 * ks + 1][1], aH[2], aL[2]);
            pack_hilo(sAcc[2 * ks + 1][2], sAcc[2 * ks + 1][3], aH[3], aL[3]);

            uint32_t vH[4][4], vL[4][4];
            #pragma unroll
            for (int nt2 = 0; nt2 < 4; nt2++) {
                uint32_t addr = u_vhi + (uint32_t)(ks * 16 + vrow_b) * TSTRB
                              + (uint32_t)(nt2 * 16) * 2 + vcol_b;
                ldmatrix_x4_trans(vH[nt2], addr);
                ldmatrix_x4_trans(vL[nt2], addr + KVT_B);
            }
            #pragma unroll
            for (int nt = 0; nt < 8; nt++) {
                const uint32_t* bh = &vH[nt >> 1][(nt & 1) * 2];
                const uint32_t* bl = &vL[nt >> 1][(nt & 1) * 2];
                mma_bf16(oAcc[nt], aH, bh, oAcc[nt]);
                mma_bf16(oAcc[nt], aL, bh, oAcc[nt]);
                mma_bf16(oAcc[nt], aH, bl, oAcc[nt]);
            }
        }
    }

    // ---- epilogue ----
    float i0 = 1.f / l0, i1 = 1.f / l1;
    const int r  = lane >> 2;
    const int c2 = (lane & 3) * 2;
    const int row0 = q0 + wid * 16 + r;
    #pragma unroll
    for (int nt = 0; nt < 8; nt++) {
        int col = h * DH + nt * 8 + c2;
        float2 oA = make_float2(oAcc[nt][0] * i0, oAcc[nt][1] * i0);
        float2 oB = make_float2(oAcc[nt][2] * i1, oAcc[nt][3] * i1);
        *(float2*)(out + (size_t)(b * SEQ + row0) * DM + col) = oA;
        *(float2*)(out + (size_t)(b * SEQ + row0 + 8) * DM + col) = oB;
    }
}

// ---------------------------------------------------------------------------
extern "C" void kernel_launch(void* const* d_in, const int* in_sizes, int n_in,
                              void* d_out, int out_size) {
    const float* query = (const float*)d_in[0];
    const float* key_t = (const float*)d_in[1];
    const float* value = (const float*)d_in[2];
    const int*   mask  = (const int*)  d_in[3];
    const float* Wq = (const float*)d_in[4];
    const float* bq = (const float*)d_in[5];
    const float* Wk = (const float*)d_in[6];
    const float* bk = (const float*)d_in[7];
    const float* Wv = (const float*)d_in[8];
    const float* bv = (const float*)d_in[9];
    const float* Wo = (const float*)d_in[10];
    const float* bo = (const float*)d_in[11];
    float* out = (float*)d_out;

    float *q, *k, *v, *attn;
    cudaGetSymbolAddress((void**)&q,    g_q);
    cudaGetSymbolAddress((void**)&k,    g_k);
    cudaGetSymbolAddress((void**)&v,    g_v);
    cudaGetSymbolAddress((void**)&attn, g_attn);

    const int M = BATCH * SEQ;       // 4096

    cudaFuncSetAttribute(gemm_tc_kernel,
                         cudaFuncAttributeMaxDynamicSharedMemorySize, GEMM_SMEM);
    cudaFuncSetAttribute(attn_tc_kernel,
                         cudaFuncAttributeMaxDynamicSharedMemorySize, ATT_SMEM);

    dim3 ggrid(DM / 128, M / 128);   // (8, 32)
    gemm_tc_kernel<<<ggrid, 256, GEMM_SMEM>>>(query, Wq, bq, q, M, DM, DM);
    gemm_tc_kernel<<<ggrid, 256, GEMM_SMEM>>>(key_t, Wk, bk, k, M, DM, DM);
    gemm_tc_kernel<<<ggrid, 256, GEMM_SMEM>>>(value, Wv, bv, v, M, DM, DM);

    dim3 agrid(SEQ / 64, NH, BATCH); // (32, 16, 2)
    attn_tc_kernel<<<agrid, 128, ATT_SMEM>>>(q, k, v, mask, attn);

    gemm_tc_kernel<<<ggrid, 256, GEMM_SMEM>>>(attn, Wo, bo, out, M, DM, DM);
}

// round 6
// speedup vs baseline: 1.3184x; 1.3184x over previous
#include <cuda_runtime.h>
#include <cuda_bf16.h>
#include <stdint.h>
#include <math.h>

#define BATCH 2
#define SEQ   2048
#define DM    1024
#define NH    16
#define DH    64
#define MELEMS (BATCH*SEQ*DM)   // 4194304
#define WELEMS (DM*DM)          // 1048576

// ---- split-bf16 scratch (allocation-free rule: __device__ globals) ----
__device__ __nv_bfloat16 g_qin_hi[MELEMS], g_qin_lo[MELEMS];
__device__ __nv_bfloat16 g_kin_hi[MELEMS], g_kin_lo[MELEMS];
__device__ __nv_bfloat16 g_vin_hi[MELEMS], g_vin_lo[MELEMS];
__device__ __nv_bfloat16 g_wq_hi[WELEMS], g_wq_lo[WELEMS];
__device__ __nv_bfloat16 g_wk_hi[WELEMS], g_wk_lo[WELEMS];
__device__ __nv_bfloat16 g_wv_hi[WELEMS], g_wv_lo[WELEMS];
__device__ __nv_bfloat16 g_wo_hi[WELEMS], g_wo_lo[WELEMS];
__device__ __nv_bfloat16 g_Q_hi[MELEMS], g_Q_lo[MELEMS];
__device__ __nv_bfloat16 g_K_hi[MELEMS], g_K_lo[MELEMS];
__device__ __nv_bfloat16 g_V_hi[MELEMS], g_V_lo[MELEMS];
__device__ __nv_bfloat16 g_at_hi[MELEMS], g_at_lo[MELEMS];

// ============================================================================
// Helpers
// ============================================================================
__device__ __forceinline__ uint32_t smem_u32(const void* p) {
    uint32_t a;
    asm("{ .reg .u64 t; cvta.to.shared.u64 t, %1; cvt.u32.u64 %0, t; }"
        : "=r"(a) : "l"(p));
    return a;
}

__device__ __forceinline__ void cp_async16(uint32_t dst, const void* src) {
    asm volatile("cp.async.cg.shared.global [%0], [%1], 16;"
                 :: "r"(dst), "l"(src) : "memory");
}
#define CP_COMMIT() asm volatile("cp.async.commit_group;" ::: "memory")
#define CP_WAIT0()  asm volatile("cp.async.wait_group 0;" ::: "memory")

__device__ __forceinline__ void ldmatrix_x4(uint32_t* r, uint32_t addr) {
    asm volatile("ldmatrix.sync.aligned.m8n8.x4.shared.b16 {%0,%1,%2,%3}, [%4];"
                 : "=r"(r[0]), "=r"(r[1]), "=r"(r[2]), "=r"(r[3]) : "r"(addr));
}
__device__ __forceinline__ void ldmatrix_x4_trans(uint32_t* r, uint32_t addr) {
    asm volatile("ldmatrix.sync.aligned.m8n8.x4.trans.shared.b16 {%0,%1,%2,%3}, [%4];"
                 : "=r"(r[0]), "=r"(r[1]), "=r"(r[2]), "=r"(r[3]) : "r"(addr));
}
__device__ __forceinline__ void mma_bf16(float* d, const uint32_t* a, const uint32_t* b,
                                         const float* c) {
    asm volatile(
        "mma.sync.aligned.m16n8k16.row.col.f32.bf16.bf16.f32 "
        "{%0,%1,%2,%3}, {%4,%5,%6,%7}, {%8,%9}, {%10,%11,%12,%13};"
        : "=f"(d[0]), "=f"(d[1]), "=f"(d[2]), "=f"(d[3])
        : "r"(a[0]), "r"(a[1]), "r"(a[2]), "r"(a[3]),
          "r"(b[0]), "r"(b[1]),
          "f"(c[0]), "f"(c[1]), "f"(c[2]), "f"(c[3]));
}
__device__ __forceinline__ void pack_hilo(float x, float y, uint32_t& hi, uint32_t& lo) {
    __nv_bfloat16 hx = __float2bfloat16(x);
    __nv_bfloat16 hy = __float2bfloat16(y);
    __nv_bfloat16 lx = __float2bfloat16(x - __bfloat162float(hx));
    __nv_bfloat16 ly = __float2bfloat16(y - __bfloat162float(hy));
    hi = (uint32_t)__bfloat16_as_ushort(hx) | ((uint32_t)__bfloat16_as_ushort(hy) << 16);
    lo = (uint32_t)__bfloat16_as_ushort(lx) | ((uint32_t)__bfloat16_as_ushort(ly) << 16);
}

#define TSTRB 144   // 9 * 16B: conflict-free, 16B-aligned rows

// ============================================================================
// Pre-pass: fp32 -> hi/lo bf16 split
// ============================================================================
__global__ void split_kernel(const float4* __restrict__ src, uint2* __restrict__ hi,
                             uint2* __restrict__ lo, int n4) {
    int i = blockIdx.x * 256 + threadIdx.x;
    if (i >= n4) return;
    float4 v = src[i];
    uint2 hp, lp;
    uint32_t h01, l01, h23, l23;
    pack_hilo(v.x, v.y, h01, l01);
    pack_hilo(v.z, v.w, h23, l23);
    hp.x = h01; hp.y = h23; lp.x = l01; lp.y = l23;
    hi[i] = hp; lo[i] = lp;
}

// ============================================================================
// Pre-split GEMM:  C[M,N] = (A @ W^T + bias) * scale
// A, W pre-split bf16 hi/lo. 128x128 tile, K-chunk 64, cp.async double buffer.
// 3-pass: AhiWhi + AhiWlo + AloWhi. OUT_SPLIT: write hi/lo bf16; else fp32.
// Stage layout (73728 B): Ahi +0, Alo +18432, Bhi +36864, Blo +55296.
// ============================================================================
#define G_STG   73728
#define GEMM_PS_SMEM (2 * G_STG)   // 147456

template<int OUT_SPLIT>
__global__ void __launch_bounds__(256) gemm_ps_kernel(
    const __nv_bfloat16* __restrict__ Ahi, const __nv_bfloat16* __restrict__ Alo,
    const __nv_bfloat16* __restrict__ Whi, const __nv_bfloat16* __restrict__ Wlo,
    const float* __restrict__ bias,
    float* __restrict__ Cf, __nv_bfloat16* __restrict__ Chi, __nv_bfloat16* __restrict__ Clo,
    float scale, int M, int N, int K)
{
    extern __shared__ char sm[];
    const int tid = threadIdx.x;
    const int wid = tid >> 5;
    const int lane = tid & 31;
    const int m0 = blockIdx.y * 128;
    const int n0 = blockIdx.x * 128;
    const int wm = wid >> 1;
    const int wn = wid & 1;
    const uint32_t u = smem_u32(sm);

    const __nv_bfloat16* const srcA[2] = {Ahi, Alo};
    const __nv_bfloat16* const srcB[2] = {Whi, Wlo};

    // issue K-chunk c into stage s (16 cp.async per thread)
    auto issue = [&](int c, int s) {
        const int k0 = c * 64;
        const uint32_t sb = u + s * G_STG;
        #pragma unroll
        for (int half = 0; half < 2; half++)
            #pragma unroll
            for (int j = 0; j < 4; j++) {
                int cc = tid + j * 256;        // 1024 chunks per buffer
                int row = cc >> 3, ch = cc & 7;
                cp_async16(sb + half * 18432 + row * TSTRB + ch * 16,
                           srcA[half] + (size_t)(m0 + row) * K + k0 + ch * 8);
                cp_async16(sb + 36864 + half * 18432 + row * TSTRB + ch * 16,
                           srcB[half] + (size_t)(n0 + row) * K + k0 + ch * 8);
            }
    };

    float acc[2][8][4];
    #pragma unroll
    for (int i = 0; i < 2; i++)
        #pragma unroll
        for (int j = 0; j < 8; j++)
            #pragma unroll
            for (int t = 0; t < 4; t++) acc[i][j][t] = 0.f;

    const uint32_t a_row = (uint32_t)(wm * 32 + (lane & 15));
    const uint32_t a_kof = (uint32_t)((lane >> 4) * 8) * 2;
    const uint32_t b_row = (uint32_t)(wn * 64 + (lane & 7) + ((lane >> 4) & 1) * 8);
    const uint32_t b_kof = (uint32_t)(((lane >> 3) & 1) * 8) * 2;

    issue(0, 0); CP_COMMIT();

    const int nchunk = K / 64;   // 16
    for (int c = 0; c < nchunk; ++c) {
        const int cur = c & 1;
        CP_WAIT0();
        __syncthreads();
        if (c + 1 < nchunk) { issue(c + 1, cur ^ 1); CP_COMMIT(); }

        const uint32_t sb = u + cur * G_STG;
        #pragma unroll
        for (int ks = 0; ks < 4; ks++) {
            const uint32_t kbyte = (uint32_t)(ks * 16) * 2;
            uint32_t aHi[2][4], aLo[2][4], bHi[4][4], bLo[4][4];
            #pragma unroll
            for (int mi = 0; mi < 2; mi++) {
                uint32_t ar = sb + (a_row + mi * 16) * TSTRB + kbyte + a_kof;
                ldmatrix_x4(aHi[mi], ar);
                ldmatrix_x4(aLo[mi], ar + 18432);
            }
            #pragma unroll
            for (int nt2 = 0; nt2 < 4; nt2++) {
                uint32_t br = sb + 36864 + (b_row + nt2 * 16) * TSTRB + kbyte + b_kof;
                ldmatrix_x4(bHi[nt2], br);
                ldmatrix_x4(bLo[nt2], br + 18432);
            }
            #pragma unroll
            for (int mi = 0; mi < 2; mi++)
                #pragma unroll
                for (int nt = 0; nt < 8; nt++) {
                    const uint32_t* bh = &bHi[nt >> 1][(nt & 1) * 2];
                    const uint32_t* bl = &bLo[nt >> 1][(nt & 1) * 2];
                    mma_bf16(acc[mi][nt], aHi[mi], bh, acc[mi][nt]);
                    mma_bf16(acc[mi][nt], aHi[mi], bl, acc[mi][nt]);
                    mma_bf16(acc[mi][nt], aLo[mi], bh, acc[mi][nt]);
                }
        }
    }

    const int er = lane >> 2;
    const int ec = (lane & 3) * 2;
    #pragma unroll
    for (int mi = 0; mi < 2; mi++) {
        int row0 = m0 + wm * 32 + mi * 16 + er;
        #pragma unroll
        for (int nt = 0; nt < 8; nt++) {
            int col = n0 + wn * 64 + nt * 8 + ec;
            float b0 = __ldg(bias + col), b1 = __ldg(bias + col + 1);
            if (OUT_SPLIT) {
                float v0 = (acc[mi][nt][0] + b0) * scale;
                float v1 = (acc[mi][nt][1] + b1) * scale;
                float v2 = (acc[mi][nt][2] + b0) * scale;
                float v3 = (acc[mi][nt][3] + b1) * scale;
                uint32_t h01, l01, h23, l23;
                pack_hilo(v0, v1, h01, l01);
                pack_hilo(v2, v3, h23, l23);
                *(uint32_t*)(Chi + (size_t)row0 * N + col) = h01;
                *(uint32_t*)(Clo + (size_t)row0 * N + col) = l01;
                *(uint32_t*)(Chi + (size_t)(row0 + 8) * N + col) = h23;
                *(uint32_t*)(Clo + (size_t)(row0 + 8) * N + col) = l23;
            } else {
                float2 o0 = make_float2(acc[mi][nt][0] + b0, acc[mi][nt][1] + b1);
                float2 o1 = make_float2(acc[mi][nt][2] + b0, acc[mi][nt][3] + b1);
                *(float2*)(Cf + (size_t)row0 * N + col) = o0;
                *(float2*)(Cf + (size_t)(row0 + 8) * N + col) = o1;
            }
        }
    }
}

// ============================================================================
// Pre-split tensor-core flash attention. CTA = (b, h, 128 q-rows), 8 warps.
// KV tile 64, cp.async double-buffered stages. 3-pass QK^T and PV.
// Stage (36864 B): Khi +0, Klo +9216, Vhi +18432, Vlo +27648.
// Mask: int[2][64] at 73728. Q staged in stage0 region during phase 1.
// ============================================================================
#define A_STG 36864
#define ATT_PS_SMEM (2 * A_STG + 512)   // 74240

__global__ void __launch_bounds__(256) attn_ps_kernel(
    const __nv_bfloat16* __restrict__ qhi, const __nv_bfloat16* __restrict__ qlo,
    const __nv_bfloat16* __restrict__ khi, const __nv_bfloat16* __restrict__ klo,
    const __nv_bfloat16* __restrict__ vhi, const __nv_bfloat16* __restrict__ vlo,
    const int* __restrict__ mask,
    __nv_bfloat16* __restrict__ ohi, __nv_bfloat16* __restrict__ olo)
{
    extern __shared__ char sm[];
    const int b  = blockIdx.z;
    const int h  = blockIdx.y;
    const int q0 = blockIdx.x * 128;
    const int tid  = threadIdx.x;
    const int wid  = tid >> 5;
    const int lane = tid & 31;
    const uint32_t u = smem_u32(sm);

    // ---- Phase 1: stage Q hi/lo (pre-scaled by 0.125 at projection) ----
    {
        const __nv_bfloat16* const srcQ[2] = {qhi, qlo};
        #pragma unroll
        for (int half = 0; half < 2; half++)
            #pragma unroll
            for (int j = 0; j < 4; j++) {
                int cc = tid + j * 256;        // 1024 chunks per buffer (128 rows x 8)
                int row = cc >> 3, ch = cc & 7;
                cp_async16(u + half * 18432 + row * TSTRB + ch * 16,
                           srcQ[half] + (size_t)(b * SEQ + q0 + row) * DM + h * DH + ch * 8);
            }
        CP_COMMIT();
        CP_WAIT0();
        __syncthreads();
    }

    uint32_t qHi[4][4], qLo[4][4];
    {
        const uint32_t qrow = (uint32_t)(wid * 16 + (lane & 15));
        const uint32_t qkof = (uint32_t)((lane >> 4) * 8) * 2;
        #pragma unroll
        for (int ks = 0; ks < 4; ks++) {
            uint32_t addr = u + qrow * TSTRB + (uint32_t)(ks * 32) + qkof;
            ldmatrix_x4(qHi[ks], addr);
            ldmatrix_x4(qLo[ks], addr + 18432);
        }
    }
    __syncthreads();   // Q smem region now reusable as KV stage 0

    const __nv_bfloat16* const srcKV[4] = {khi, klo, vhi, vlo};
    auto issue = [&](int j0, int s) {
        const uint32_t sb = u + s * A_STG;
        #pragma unroll
        for (int buf = 0; buf < 4; buf++)
            #pragma unroll
            for (int j = 0; j < 2; j++) {
                int cc = tid + j * 256;        // 512 chunks per buffer (64 rows x 8)
                int row = cc >> 3, ch = cc & 7;
                cp_async16(sb + buf * 9216 + row * TSTRB + ch * 16,
                           srcKV[buf] + (size_t)(b * SEQ + j0 + row) * DM + h * DH + ch * 8);
            }
        if (tid < 16)
            cp_async16(u + 2 * A_STG + s * 256 + tid * 16,
                       mask + b * SEQ + j0 + tid * 4);
    };

    // ---- main loop state ----
    float m0 = -1e30f, m1 = -1e30f, l0 = 0.f, l1 = 0.f;
    float oAcc[8][4];
    #pragma unroll
    for (int nt = 0; nt < 8; nt++)
        #pragma unroll
        for (int t = 0; t < 4; t++) oAcc[nt][t] = 0.f;

    const uint32_t krow_b = (uint32_t)((lane & 7) + ((lane >> 4) & 1) * 8);
    const uint32_t kk_b   = (uint32_t)(((lane >> 3) & 1) * 8) * 2;
    const uint32_t vrow_b = (uint32_t)(lane & 15);
    const uint32_t vcol_b = (uint32_t)(((lane >> 4) & 1) * 8) * 2;
    const int mcol = (lane & 3) * 2;

    issue(0, 0); CP_COMMIT();

    const int ntiles = SEQ / 64;   // 32
    for (int t = 0; t < ntiles; ++t) {
        const int cur = t & 1;
        CP_WAIT0();
        __syncthreads();
        if (t + 1 < ntiles) { issue((t + 1) * 64, cur ^ 1); CP_COMMIT(); }

        const uint32_t sb = u + cur * A_STG;
        const int* mcur = (const int*)(sm + 2 * A_STG + cur * 256);

        // ---- S = Q @ K^T (3 passes) ----
        float sAcc[8][4];
        #pragma unroll
        for (int nt = 0; nt < 8; nt++)
            #pragma unroll
            for (int tt = 0; tt < 4; tt++) sAcc[nt][tt] = 0.f;

        #pragma unroll
        for (int ks = 0; ks < 4; ks++) {
            const uint32_t kbyte = (uint32_t)(ks * 16) * 2;
            uint32_t kH[4][4], kL[4][4];
            #pragma unroll
            for (int nt2 = 0; nt2 < 4; nt2++) {
                uint32_t addr = sb + (uint32_t)(nt2 * 16 + krow_b) * TSTRB + kbyte + kk_b;
                ldmatrix_x4(kH[nt2], addr);
                ldmatrix_x4(kL[nt2], addr + 9216);
            }
            #pragma unroll
            for (int nt = 0; nt < 8; nt++) {
                const uint32_t* bh = &kH[nt >> 1][(nt & 1) * 2];
                const uint32_t* bl = &kL[nt >> 1][(nt & 1) * 2];
                mma_bf16(sAcc[nt], qHi[ks], bh, sAcc[nt]);
                mma_bf16(sAcc[nt], qHi[ks], bl, sAcc[nt]);
                mma_bf16(sAcc[nt], qLo[ks], bh, sAcc[nt]);
            }
        }

        // ---- mask + online softmax ----
        float rm0 = -1e30f, rm1 = -1e30f;
        #pragma unroll
        for (int nt = 0; nt < 8; nt++) {
            int2 mf = *(const int2*)(mcur + nt * 8 + mcol);
            float s0 = (mf.x != 0) ? sAcc[nt][0] : -1e9f;
            float s1 = (mf.y != 0) ? sAcc[nt][1] : -1e9f;
            float s2 = (mf.x != 0) ? sAcc[nt][2] : -1e9f;
            float s3 = (mf.y != 0) ? sAcc[nt][3] : -1e9f;
            sAcc[nt][0] = s0; sAcc[nt][1] = s1; sAcc[nt][2] = s2; sAcc[nt][3] = s3;
            rm0 = fmaxf(rm0, fmaxf(s0, s1));
            rm1 = fmaxf(rm1, fmaxf(s2, s3));
        }
        rm0 = fmaxf(rm0, __shfl_xor_sync(0xffffffffu, rm0, 1));
        rm0 = fmaxf(rm0, __shfl_xor_sync(0xffffffffu, rm0, 2));
        rm1 = fmaxf(rm1, __shfl_xor_sync(0xffffffffu, rm1, 1));
        rm1 = fmaxf(rm1, __shfl_xor_sync(0xffffffffu, rm1, 2));

        float m0n = fmaxf(m0, rm0), m1n = fmaxf(m1, rm1);
        float a0 = __expf(m0 - m0n), a1 = __expf(m1 - m1n);
        float ps0 = 0.f, ps1 = 0.f;
        #pragma unroll
        for (int nt = 0; nt < 8; nt++) {
            float p0 = __expf(sAcc[nt][0] - m0n);
            float p1 = __expf(sAcc[nt][1] - m0n);
            float p2 = __expf(sAcc[nt][2] - m1n);
            float p3 = __expf(sAcc[nt][3] - m1n);
            sAcc[nt][0] = p0; sAcc[nt][1] = p1; sAcc[nt][2] = p2; sAcc[nt][3] = p3;
            ps0 += p0 + p1; ps1 += p2 + p3;
            oAcc[nt][0] *= a0; oAcc[nt][1] *= a0;
            oAcc[nt][2] *= a1; oAcc[nt][3] *= a1;
        }
        ps0 += __shfl_xor_sync(0xffffffffu, ps0, 1);
        ps0 += __shfl_xor_sync(0xffffffffu, ps0, 2);
        ps1 += __shfl_xor_sync(0xffffffffu, ps1, 1);
        ps1 += __shfl_xor_sync(0xffffffffu, ps1, 2);
        l0 = l0 * a0 + ps0;
        l1 = l1 * a1 + ps1;
        m0 = m0n; m1 = m1n;

        // ---- O += P @ V (3 passes) ----
        #pragma unroll
        for (int ks = 0; ks < 4; ks++) {
            uint32_t aH[4], aL[4];
            pack_hilo(sAcc[2 * ks][0],     sAcc[2 * ks][1],     aH[0], aL[0]);
            pack_hilo(sAcc[2 * ks][2],     sAcc[2 * ks][3],     aH[1], aL[1]);
            pack_hilo(sAcc[2 * ks + 1][0], sAcc[2 * ks + 1][1], aH[2], aL[2]);
            pack_hilo(sAcc[2 * ks + 1][2], sAcc[2 * ks + 1][3], aH[3], aL[3]);

            uint32_t vH[4][4], vL[4][4];
            #pragma unroll
            for (int nt2 = 0; nt2 < 4; nt2++) {
                uint32_t addr = sb + 18432 + (uint32_t)(ks * 16 + vrow_b) * TSTRB
                              + (uint32_t)(nt2 * 16) * 2 + vcol_b;
                ldmatrix_x4_trans(vH[nt2], addr);
                ldmatrix_x4_trans(vL[nt2], addr + 9216);
            }
            #pragma unroll
            for (int nt = 0; nt < 8; nt++) {
                const uint32_t* bh = &vH[nt >> 1][(nt & 1) * 2];
                const uint32_t* bl = &vL[nt >> 1][(nt & 1) * 2];
                mma_bf16(oAcc[nt], aH, bh, oAcc[nt]);
                mma_bf16(oAcc[nt], aL, bh, oAcc[nt]);
                mma_bf16(oAcc[nt], aH, bl, oAcc[nt]);
            }
        }
    }

    // ---- epilogue: write split bf16 attention output ----
    float i0 = 1.f / l0, i1 = 1.f / l1;
    const int r  = lane >> 2;
    const int c2 = (lane & 3) * 2;
    const int row0 = q0 + wid * 16 + r;
    #pragma unroll
    for (int nt = 0; nt < 8; nt++) {
        int col = h * DH + nt * 8 + c2;
        uint32_t h01, l01, h23, l23;
        pack_hilo(oAcc[nt][0] * i0, oAcc[nt][1] * i0, h01, l01);
        pack_hilo(oAcc[nt][2] * i1, oAcc[nt][3] * i1, h23, l23);
        *(uint32_t*)(ohi + (size_t)(b * SEQ + row0) * DM + col) = h01;
        *(uint32_t*)(olo + (size_t)(b * SEQ + row0) * DM + col) = l01;
        *(uint32_t*)(ohi + (size_t)(b * SEQ + row0 + 8) * DM + col) = h23;
        *(uint32_t*)(olo + (size_t)(b * SEQ + row0 + 8) * DM + col) = l23;
    }
}

// ---------------------------------------------------------------------------
extern "C" void kernel_launch(void* const* d_in, const int* in_sizes, int n_in,
                              void* d_out, int out_size) {
    const float* query = (const float*)d_in[0];
    const float* key_t = (const float*)d_in[1];
    const float* value = (const float*)d_in[2];
    const int*   mask  = (const int*)  d_in[3];
    const float* Wq = (const float*)d_in[4];
    const float* bq = (const float*)d_in[5];
    const float* Wk = (const float*)d_in[6];
    const float* bk = (const float*)d_in[7];
    const float* Wv = (const float*)d_in[8];
    const float* bv = (const float*)d_in[9];
    const float* Wo = (const float*)d_in[10];
    const float* bo = (const float*)d_in[11];
    float* out = (float*)d_out;

    __nv_bfloat16 *qin_hi, *qin_lo, *kin_hi, *kin_lo, *vin_hi, *vin_lo;
    __nv_bfloat16 *wq_hi, *wq_lo, *wk_hi, *wk_lo, *wv_hi, *wv_lo, *wo_hi, *wo_lo;
    __nv_bfloat16 *Q_hi, *Q_lo, *K_hi, *K_lo, *V_hi, *V_lo, *at_hi, *at_lo;
    cudaGetSymbolAddress((void**)&qin_hi, g_qin_hi);
    cudaGetSymbolAddress((void**)&qin_lo, g_qin_lo);
    cudaGetSymbolAddress((void**)&kin_hi, g_kin_hi);
    cudaGetSymbolAddress((void**)&kin_lo, g_kin_lo);
    cudaGetSymbolAddress((void**)&vin_hi, g_vin_hi);
    cudaGetSymbolAddress((void**)&vin_lo, g_vin_lo);
    cudaGetSymbolAddress((void**)&wq_hi, g_wq_hi);
    cudaGetSymbolAddress((void**)&wq_lo, g_wq_lo);
    cudaGetSymbolAddress((void**)&wk_hi, g_wk_hi);
    cudaGetSymbolAddress((void**)&wk_lo, g_wk_lo);
    cudaGetSymbolAddress((void**)&wv_hi, g_wv_hi);
    cudaGetSymbolAddress((void**)&wv_lo, g_wv_lo);
    cudaGetSymbolAddress((void**)&wo_hi, g_wo_hi);
    cudaGetSymbolAddress((void**)&wo_lo, g_wo_lo);
    cudaGetSymbolAddress((void**)&Q_hi, g_Q_hi);
    cudaGetSymbolAddress((void**)&Q_lo, g_Q_lo);
    cudaGetSymbolAddress((void**)&K_hi, g_K_hi);
    cudaGetSymbolAddress((void**)&K_lo, g_K_lo);
    cudaGetSymbolAddress((void**)&V_hi, g_V_hi);
    cudaGetSymbolAddress((void**)&V_lo, g_V_lo);
    cudaGetSymbolAddress((void**)&at_hi, g_at_hi);
    cudaGetSymbolAddress((void**)&at_lo, g_at_lo);

    const int M = BATCH * SEQ;       // 4096
    const int n4m = MELEMS / 4;      // 1048576
    const int n4w = WELEMS / 4;      // 262144

    cudaFuncSetAttribute(gemm_ps_kernel<0>,
                         cudaFuncAttributeMaxDynamicSharedMemorySize, GEMM_PS_SMEM);
    cudaFuncSetAttribute(gemm_ps_kernel<1>,
                         cudaFuncAttributeMaxDynamicSharedMemorySize, GEMM_PS_SMEM);
    cudaFuncSetAttribute(attn_ps_kernel,
                         cudaFuncAttributeMaxDynamicSharedMemorySize, ATT_PS_SMEM);

    // Pre-pass splits
    split_kernel<<<(n4m + 255) / 256, 256>>>((const float4*)query, (uint2*)qin_hi, (uint2*)qin_lo, n4m);
    split_kernel<<<(n4m + 255) / 256, 256>>>((const float4*)key_t, (uint2*)kin_hi, (uint2*)kin_lo, n4m);
    split_kernel<<<(n4m + 255) / 256, 256>>>((const float4*)value, (uint2*)vin_hi, (uint2*)vin_lo, n4m);
    split_kernel<<<(n4w + 255) / 256, 256>>>((const float4*)Wq, (uint2*)wq_hi, (uint2*)wq_lo, n4w);
    split_kernel<<<(n4w + 255) / 256, 256>>>((const float4*)Wk, (uint2*)wk_hi, (uint2*)wk_lo, n4w);
    split_kernel<<<(n4w + 255) / 256, 256>>>((const float4*)Wv, (uint2*)wv_hi, (uint2*)wv_lo, n4w);
    split_kernel<<<(n4w + 255) / 256, 256>>>((const float4*)Wo, (uint2*)wo_hi, (uint2*)wo_lo, n4w);

    dim3 ggrid(DM / 128, M / 128);   // (8, 32)
    gemm_ps_kernel<1><<<ggrid, 256, GEMM_PS_SMEM>>>(qin_hi, qin_lo, wq_hi, wq_lo, bq,
                                                    nullptr, Q_hi, Q_lo, 0.125f, M, DM, DM);
    gemm_ps_kernel<1><<<ggrid, 256, GEMM_PS_SMEM>>>(kin_hi, kin_lo, wk_hi, wk_lo, bk,
                                                    nullptr, K_hi, K_lo, 1.0f, M, DM, DM);
    gemm_ps_kernel<1><<<ggrid, 256, GEMM_PS_SMEM>>>(vin_hi, vin_lo, wv_hi, wv_lo, bv,
                                                    nullptr, V_hi, V_lo, 1.0f, M, DM, DM);

    dim3 agrid(SEQ / 128, NH, BATCH); // (16, 16, 2)
    attn_ps_kernel<<<agrid, 256, ATT_PS_SMEM>>>(Q_hi, Q_lo, K_hi, K_lo, V_hi, V_lo,
                                                mask, at_hi, at_lo);

    gemm_ps_kernel<0><<<ggrid, 256, GEMM_PS_SMEM>>>(at_hi, at_lo, wo_hi, wo_lo, bo,
                                                    out, nullptr, nullptr, 1.0f, M, DM, DM);
}